// round 13
// baseline (speedup 1.0000x reference)
#include <cuda_runtime.h>
#include <cstdint>
#include <math.h>

// Problem constants
#define Bc 8
#define Tc 1024
#define Ec 1024
#define Hc 16
#define Dc 64
#define Mc (Bc * Tc)          // 8192
#define NREL (2 * Tc - 1)     // 2047

// Scratch (static device globals; no cudaMalloc allowed)
__device__ float g_q[(size_t)Bc * Hc * Tc * Dc];   // [B,H,T,D] rounded, d-permuted
__device__ float g_k[(size_t)Bc * Hc * Tc * Dc];   // rounded, d-permuted
__device__ float g_v[(size_t)Bc * Hc * Tc * Dc];   // rounded, plain d
__device__ float g_ao[(size_t)Bc * Hc * Tc * Dc];  // attn out, rounded+permuted
__device__ float g_bias[Hc * NREL];                // bias_rel[h][r]
__device__ float g_ar[(size_t)3 * Mc * Ec];        // rounded+permuted A (q,k,v)
__device__ float g_wr[(size_t)4 * Ec * Ec];        // rounded+permuted W (q,k,v,o)

// k-permutation within each 16-group: slot(k) = 4(k&3) + 2((k>>3)&1) + ((k>>2)&1)
__device__ __forceinline__ int perm16(int k) {
    return 4 * (k & 3) + 2 * ((k >> 3) & 1) + ((k >> 2) & 1);
}

// ---------------------------------------------------------------------------
// tf32 + cp.async helpers (baseline PTX — compiles at target sm_103)
// ---------------------------------------------------------------------------
__device__ __forceinline__ uint32_t f2t(float x) {
    uint32_t r;
    asm("cvt.rna.tf32.f32 %0, %1;" : "=r"(r) : "f"(x));
    return r;
}
__device__ __forceinline__ float f2tf(float x) { return __uint_as_float(f2t(x)); }

__device__ __forceinline__ void mma8(float* c, uint32_t a0, uint32_t a1,
                                     uint32_t a2, uint32_t a3, uint32_t b0,
                                     uint32_t b1) {
    asm volatile(
        "mma.sync.aligned.m16n8k8.row.col.f32.tf32.tf32.f32 "
        "{%0,%1,%2,%3}, {%4,%5,%6,%7}, {%8,%9}, {%0,%1,%2,%3};"
        : "+f"(c[0]), "+f"(c[1]), "+f"(c[2]), "+f"(c[3])
        : "r"(a0), "r"(a1), "r"(a2), "r"(a3), "r"(b0), "r"(b1));
}
#define U(x) __float_as_uint(x)

__device__ __forceinline__ uint32_t smem_to_u32(const void* p) {
    uint32_t a;
    asm("{ .reg .u64 t; cvta.to.shared.u64 t, %1; cvt.u32.u64 %0, t; }"
        : "=r"(a) : "l"(p));
    return a;
}
__device__ __forceinline__ void cp16(uint32_t dst, const float* src) {
    asm volatile("cp.async.cg.shared.global [%0], [%1], 16;"
                 :: "r"(dst), "l"(src));
}
#define CP_COMMIT() asm volatile("cp.async.commit_group;" ::: "memory")
#define CP_WAIT0() asm volatile("cp.async.wait_group 0;" ::: "memory")
#define CP_WAIT1() asm volatile("cp.async.wait_group 1;" ::: "memory")

// ---------------------------------------------------------------------------
// Kernel: precompute interpolated relative bias per (h, rel)
// ---------------------------------------------------------------------------
__global__ void bias_kernel(const float* __restrict__ table,
                            const float* __restrict__ offset) {
    float bounded = tanhf(offset[0]) * 0.5f;
    for (int idx = blockIdx.x * blockDim.x + threadIdx.x; idx < Hc * NREL;
         idx += gridDim.x * blockDim.x) {
        int h = idx / NREL;
        int r = idx - h * NREL;
        float adj = (float)r + bounded;
        adj = fminf(fmaxf(adj, 0.0f), (float)(NREL - 1));
        int lo = (int)floorf(adj);
        int hi = (int)ceilf(adj);
        float w = adj - (float)lo;
        g_bias[h * NREL + r] =
            table[lo * Hc + h] * (1.0f - w) + table[hi * Hc + h] * w;
    }
}

// ---------------------------------------------------------------------------
// Conversion: tf32-round + 4x4 transpose within each 16-k group.
// ---------------------------------------------------------------------------
__device__ __forceinline__ void round_perm16(const float4* in, float4* out) {
    float4 x0 = in[0], x1 = in[1], x2 = in[2], x3 = in[3];
    out[0] = {f2tf(x0.x), f2tf(x1.x), f2tf(x2.x), f2tf(x3.x)};
    out[1] = {f2tf(x0.y), f2tf(x1.y), f2tf(x2.y), f2tf(x3.y)};
    out[2] = {f2tf(x0.z), f2tf(x1.z), f2tf(x2.z), f2tf(x3.z)};
    out[3] = {f2tf(x0.w), f2tf(x1.w), f2tf(x2.w), f2tf(x3.w)};
}

__global__ void conv_perm3(const float* __restrict__ s0,
                           const float* __restrict__ s1,
                           const float* __restrict__ s2) {
    const int n16 = Mc * Ec / 16;
    for (int idx = blockIdx.x * blockDim.x + threadIdx.x; idx < 3 * n16;
         idx += gridDim.x * blockDim.x) {
        int a = idx / n16, r = idx - a * n16;
        const float* s = (a == 0) ? s0 : ((a == 1) ? s1 : s2);
        float4 o[4];
        round_perm16((const float4*)(s + (size_t)r * 16), o);
        float4* d = (float4*)(g_ar + (size_t)a * (Mc * Ec) + (size_t)r * 16);
        d[0] = o[0]; d[1] = o[1]; d[2] = o[2]; d[3] = o[3];
    }
}

__global__ void conv_perm4(const float* __restrict__ s0,
                           const float* __restrict__ s1,
                           const float* __restrict__ s2,
                           const float* __restrict__ s3) {
    const int n16 = Ec * Ec / 16;
    for (int idx = blockIdx.x * blockDim.x + threadIdx.x; idx < 4 * n16;
         idx += gridDim.x * blockDim.x) {
        int a = idx / n16, r = idx - a * n16;
        const float* s = (a == 0) ? s0 : ((a == 1) ? s1 : ((a == 2) ? s2 : s3));
        float4 o[4];
        round_perm16((const float4*)(s + (size_t)r * 16), o);
        float4* d = (float4*)(g_wr + (size_t)a * (Ec * Ec) + (size_t)r * 16);
        d[0] = o[0]; d[1] = o[1]; d[2] = o[2]; d[3] = o[3];
    }
}

// ---------------------------------------------------------------------------
// tf32 mma.sync GEMM v4: occupancy experiment.
// CTA tile 128x64, warp tile 32x32 (4m x 2n warps), acc 32 regs/thread,
// __launch_bounds__(256,3) -> 24 warps/SM.  3-stage cp.async, LDS.128 frags,
// XOR-swizzled rows of 32 floats.
// ---------------------------------------------------------------------------
#define KC 32
#define NCH (Ec / KC)            // 32
#define A_F (128 * 32)           // 4096 floats A per stage
#define B_F (64 * 32)            // 2048 floats B per stage
#define STAGE_F (A_F + B_F)      // 6144
#define NSTAGE 3
#define SMEM_GEMM (NSTAGE * STAGE_F * 4)  // 73728 B

template <int IN_HEADS, int OUT_QKV>
__global__ __launch_bounds__(256, 3) void gemm_tc(
    const float* __restrict__ bias0, const float* __restrict__ bias1,
    const float* __restrict__ bias2, float* __restrict__ Cplain) {
    extern __shared__ float sm[];
    const uint32_t smb = smem_to_u32(sm);

    const int tid = threadIdx.x;
    const int m0 = blockIdx.y * 128;
    const int n0 = blockIdx.x * 64;
    const int z = OUT_QKV ? blockIdx.z : 3;  // W slot 3 = Wo
    const int wid = tid >> 5, lane = tid & 31;
    const int wm = wid & 3, wn = wid >> 2;
    const int q = lane & 3, g = lane >> 2;

    const float* bias =
        OUT_QKV ? (z == 0 ? bias0 : (z == 1 ? bias1 : bias2)) : bias0;

    // A fill mapping: 2 threads/row, 4 units each
    const int lr = tid >> 1;
    const int u0 = (tid & 1) * 4;
    const int asw = (lr & 1) << 2;
    // B fill mapping: 4 threads/row, 2 units each
    const int brow = tid >> 2;
    const int bu0 = (tid & 3) * 2;
    const int bsw = (brow & 1) << 2;

    const float* Wrow = g_wr + (size_t)z * (Ec * Ec) + (size_t)(n0 + brow) * Ec;
    const float* Arow =
        IN_HEADS ? nullptr
                 : g_ar + (size_t)z * (Mc * Ec) + (size_t)(m0 + lr) * Ec;

    auto fill = [&](int kt, int st) {
        uint32_t dA = smb + (uint32_t)(st * STAGE_F + lr * 32) * 4u;
        uint32_t dB = smb + (uint32_t)(st * STAGE_F + A_F + brow * 32) * 4u;
        const float* sA;
        if (IN_HEADS) {
            int m = m0 + lr, bb = m >> 10, t = m & 1023;
            // e = kt*32 + c stays within one head block: h = kt>>1
            sA = g_ao + (((size_t)(bb * Hc + (kt >> 1)) * Tc + t) * Dc +
                         (kt & 1) * 32);
        } else {
            sA = Arow + kt * KC;
        }
        const float* sW = Wrow + kt * KC;
#pragma unroll
        for (int i = 0; i < 4; i++) {
            int u = u0 + i;
            cp16(dA + (uint32_t)((u ^ asw) << 4), sA + u * 4);
        }
#pragma unroll
        for (int i = 0; i < 2; i++) {
            int u = bu0 + i;
            cp16(dB + (uint32_t)((u ^ bsw) << 4), sW + u * 4);
        }
    };

    float acc[2][4][4];
#pragma unroll
    for (int f = 0; f < 2; f++)
#pragma unroll
        for (int j = 0; j < 4; j++)
#pragma unroll
            for (int v = 0; v < 4; v++) acc[f][j][v] = 0.0f;

    fill(0, 0);
    CP_COMMIT();
    fill(1, 1);
    CP_COMMIT();

    const int swz = (g & 1) << 2;  // consume-side swizzle bit
    for (int kt = 0; kt < NCH; kt++) {
        const int st = kt % NSTAGE;
        CP_WAIT1();
        __syncthreads();
        if (kt + 2 < NCH) fill(kt + 2, (kt + 2) % NSTAGE);
        CP_COMMIT();

        const float* As = sm + st * STAGE_F;
        const float* Bs = As + A_F;
#pragma unroll
        for (int kp = 0; kp < 2; kp++) {
            const int uo = ((4 * kp + q) ^ swz) * 4;
            float4 a[2][2];
#pragma unroll
            for (int f = 0; f < 2; f++) {
                const float* ap = As + (wm * 32 + f * 16 + g) * 32 + uo;
                a[f][0] = *(const float4*)ap;
                a[f][1] = *(const float4*)(ap + 8 * 32);
            }
#pragma unroll
            for (int j = 0; j < 4; j++) {
                const float* bp = Bs + (wn * 32 + j * 8 + g) * 32 + uo;
                float4 b = *(const float4*)bp;
#pragma unroll
                for (int f = 0; f < 2; f++) {
                    mma8(acc[f][j], U(a[f][0].x), U(a[f][1].x), U(a[f][0].y),
                         U(a[f][1].y), U(b.x), U(b.y));
                    mma8(acc[f][j], U(a[f][0].z), U(a[f][1].z), U(a[f][0].w),
                         U(a[f][1].w), U(b.z), U(b.w));
                }
            }
        }
    }

    // Epilogue: row = wm*32 + f*16 + rr*8 + g, col = wn*32 + j*8 + 2q + {0,1}
#pragma unroll
    for (int f = 0; f < 2; f++) {
#pragma unroll
        for (int rr = 0; rr < 2; rr++) {
            int m = m0 + wm * 32 + f * 16 + rr * 8 + g;
#pragma unroll
            for (int j = 0; j < 4; j++) {
                int n = n0 + wn * 32 + j * 8 + 2 * q;
                float vx = acc[f][j][rr * 2 + 0] + __ldg(bias + n);
                float vy = acc[f][j][rr * 2 + 1] + __ldg(bias + n + 1);
                if (OUT_QKV) {
                    float* C = (z == 0) ? g_q : ((z == 1) ? g_k : g_v);
                    int bb = m >> 10, t = m & 1023;
                    int h = n >> 6;
                    float* dst = C + ((size_t)(bb * Hc + h) * Tc + t) * Dc;
                    int d = n & 63;
                    if (z < 2) {  // d-permuted for attention fragment loads
                        dst[(d & ~15) + perm16(d & 15)] = f2tf(vx);
                        dst[((d + 1) & ~15) + perm16((d + 1) & 15)] = f2tf(vy);
                    } else {
                        float2 v = {f2tf(vx), f2tf(vy)};
                        *(float2*)(dst + d) = v;
                    }
                } else {
                    float2 v = {vx, vy};
                    *(float2*)(Cplain + (size_t)m * Ec + n) = v;
                }
            }
        }
    }
}

// ---------------------------------------------------------------------------
// Fused attention v3 (unchanged from R12): Q/K swizzled 64-float rows with
// pre-permuted d -> LDS.128 fragments; V stride 72 row-major; double-buffered
// K/V via cp.async; bias window staged once.  8 warps x 16 q-rows.
// ---------------------------------------------------------------------------
#define OQ 0
#define OK0 (128 * 64)           // 8192
#define OK1 (OK0 + 64 * 64)      // 12288
#define OV0 (OK1 + 64 * 64)      // 16384
#define OV1 (OV0 + 64 * 72)      // 20992
#define OSB (OV1 + 64 * 72)      // 25600
#define SMEM_ATTN ((OSB + 1152) * 4)  // 107008 B

__global__ __launch_bounds__(256, 2) void attn_tc() {
    extern __shared__ float sm[];
    const uint32_t smb = smem_to_u32(sm);
    float* sb = sm + OSB;

    const int tid = threadIdx.x, wid = tid >> 5, lane = tid & 31;
    const int q = lane & 3, g = lane >> 2;
    const int bh = blockIdx.y;
    const int q0 = blockIdx.x * 128;
    const int h = bh & (Hc - 1);

    const float* Qg = g_q + ((size_t)bh * Tc + q0) * Dc;
    const float* Kg = g_k + (size_t)bh * Tc * Dc;
    const float* Vg = g_v + (size_t)bh * Tc * Dc;
    const float scale = 0.125f;

    auto fillKV = [&](int kt, int p) {
        int row = tid >> 2, uq = tid & 3;
        uint32_t dK = smb + (uint32_t)((p ? OK1 : OK0) + row * 64) * 4u;
        uint32_t dV =
            smb + (uint32_t)((p ? OV1 : OV0) + row * 72 + uq * 16) * 4u;
        const float* sK = Kg + (size_t)(kt * 64 + row) * 64;
        const float* sV = Vg + (size_t)(kt * 64 + row) * 64 + uq * 16;
        int swb = (row & 1) << 2;
#pragma unroll
        for (int i = 0; i < 4; i++) {
            int u = uq * 4 + i;
            cp16(dK + (uint32_t)((u ^ swb) << 4), sK + u * 4);
            cp16(dV + 16u * i, sV + 4 * i);
        }
    };

    // prologue: Q + KV chunk 0, bias window
    {
        int row = tid >> 1, uh = tid & 1;
        uint32_t dQ = smb + (uint32_t)(OQ + row * 64) * 4u;
        const float* sQ = Qg + row * 64;
        int swb = (row & 1) << 2;
#pragma unroll
        for (int i = 0; i < 8; i++) {
            int u = uh * 8 + i;
            cp16(dQ + (uint32_t)((u ^ swb) << 4), sQ + u * 4);
        }
    }
    fillKV(0, 0);
    CP_COMMIT();
    for (int i = tid; i < 1151; i += 256) sb[i] = g_bias[h * NREL + q0 + i];

    const int r0 = wid * 16 + g;
    float m_[2] = {-1e30f, -1e30f}, l_[2] = {0.0f, 0.0f};
    float O[8][4];
#pragma unroll
    for (int j = 0; j < 8; j++)
#pragma unroll
        for (int v = 0; v < 4; v++) O[j][v] = 0.0f;

    const int swz = (g & 1) << 2;
    for (int kt = 0; kt < Tc / 64; kt++) {
        const int p = kt & 1;
        CP_WAIT0();
        __syncthreads();
        if (kt + 1 < Tc / 64) fillKV(kt + 1, p ^ 1);
        CP_COMMIT();

        const float* Ks = sm + (p ? OK1 : OK0);
        const float* Vs = sm + (p ? OV1 : OV0);

        // phase A: S = Q K^T (warp tile 16 x 64), LDS.128 fragments
        float s[8][4];
#pragma unroll
        for (int j = 0; j < 8; j++)
#pragma unroll
            for (int v = 0; v < 4; v++) s[j][v] = 0.0f;
#pragma unroll
        for (int kp = 0; kp < 4; kp++) {
            const int uo = ((4 * kp + q) ^ swz) * 4;
            const float* ap = sm + OQ + (wid * 16 + g) * 64 + uo;
            float4 alo = *(const float4*)ap;
            float4 ahi = *(const float4*)(ap + 8 * 64);
#pragma unroll
            for (int j = 0; j < 8; j++) {
                const float* bp = Ks + (j * 8 + g) * 64 + uo;
                float4 b = *(const float4*)bp;
                mma8(s[j], U(alo.x), U(ahi.x), U(alo.y), U(ahi.y), U(b.x),
                     U(b.y));
                mma8(s[j], U(alo.z), U(ahi.z), U(alo.w), U(ahi.w), U(b.z),
                     U(b.w));
            }
        }

        // scale + bias, row maxima
        float mx0 = -1e30f, mx1 = -1e30f;
#pragma unroll
        for (int j = 0; j < 8; j++) {
            int i0 = r0 - kt * 64 - (j * 8 + 2 * q) + 1023;
            s[j][0] = s[j][0] * scale + sb[i0];
            s[j][1] = s[j][1] * scale + sb[i0 - 1];
            s[j][2] = s[j][2] * scale + sb[i0 + 8];
            s[j][3] = s[j][3] * scale + sb[i0 + 7];
            mx0 = fmaxf(mx0, fmaxf(s[j][0], s[j][1]));
            mx1 = fmaxf(mx1, fmaxf(s[j][2], s[j][3]));
        }
        mx0 = fmaxf(mx0, __shfl_xor_sync(0xffffffffu, mx0, 1));
        mx0 = fmaxf(mx0, __shfl_xor_sync(0xffffffffu, mx0, 2));
        mx1 = fmaxf(mx1, __shfl_xor_sync(0xffffffffu, mx1, 1));
        mx1 = fmaxf(mx1, __shfl_xor_sync(0xffffffffu, mx1, 2));

        float mn0 = fmaxf(m_[0], mx0), mn1 = fmaxf(m_[1], mx1);
        float corr0 = __expf(m_[0] - mn0), corr1 = __expf(m_[1] - mn1);
        float sum0 = 0.0f, sum1 = 0.0f;
#pragma unroll
        for (int j = 0; j < 8; j++) {
            s[j][0] = __expf(s[j][0] - mn0);
            s[j][1] = __expf(s[j][1] - mn0);
            s[j][2] = __expf(s[j][2] - mn1);
            s[j][3] = __expf(s[j][3] - mn1);
            sum0 += s[j][0] + s[j][1];
            sum1 += s[j][2] + s[j][3];
        }
        sum0 += __shfl_xor_sync(0xffffffffu, sum0, 1);
        sum0 += __shfl_xor_sync(0xffffffffu, sum0, 2);
        sum1 += __shfl_xor_sync(0xffffffffu, sum1, 1);
        sum1 += __shfl_xor_sync(0xffffffffu, sum1, 2);
        l_[0] = l_[0] * corr0 + sum0;
        l_[1] = l_[1] * corr1 + sum1;
        m_[0] = mn0;
        m_[1] = mn1;
#pragma unroll
        for (int j = 0; j < 8; j++) {
            O[j][0] *= corr0; O[j][1] *= corr0;
            O[j][2] *= corr1; O[j][3] *= corr1;
        }

        // phase B: O += P V (P via shuffles; V row-major stride 72)
        const int base = lane & ~3;
        const int s0l = base + (q >> 1);
        const int s1l = base + 2 + (q >> 1);
        const bool odd = (q & 1);
#pragma unroll
        for (int j = 0; j < 8; j++) {
            float t00 = __shfl_sync(0xffffffffu, s[j][0], s0l);
            float t01 = __shfl_sync(0xffffffffu, s[j][1], s0l);
            float t10 = __shfl_sync(0xffffffffu, s[j][0], s1l);
            float t11 = __shfl_sync(0xffffffffu, s[j][1], s1l);
            float t20 = __shfl_sync(0xffffffffu, s[j][2], s0l);
            float t21 = __shfl_sync(0xffffffffu, s[j][3], s0l);
            float t30 = __shfl_sync(0xffffffffu, s[j][2], s1l);
            float t31 = __shfl_sync(0xffffffffu, s[j][3], s1l);
            uint32_t a0 = f2t(odd ? t01 : t00);
            uint32_t a1 = f2t(odd ? t21 : t20);
            uint32_t a2 = f2t(odd ? t11 : t10);
            uint32_t a3 = f2t(odd ? t31 : t30);
#pragma unroll
            for (int n = 0; n < 8; n++) {
                const float* bp0 = Vs + (j * 8 + q) * 72 + n * 8 + g;
                const float* bp1 = Vs + (j * 8 + q + 4) * 72 + n * 8 + g;
                mma8(O[n], a0, a1, a2, a3, U(*bp0), U(*bp1));
            }
        }
    }

    // normalize + store rounded & k-permuted into g_ao (for the Wo GEMM)
    float inv0 = 1.0f / l_[0], inv1 = 1.0f / l_[1];
    float* Og = g_ao + ((size_t)bh * Tc + q0 + wid * 16) * Dc;
#pragma unroll
    for (int j = 0; j < 8; j++) {
        int d0 = j * 8 + 2 * q, d1 = d0 + 1;
        int p0 = (d0 & ~15) + perm16(d0 & 15);
        int p1 = (d1 & ~15) + perm16(d1 & 15);
        Og[g * 64 + p0] = f2tf(O[j][0] * inv0);
        Og[g * 64 + p1] = f2tf(O[j][1] * inv0);
        Og[(g + 8) * 64 + p0] = f2tf(O[j][2] * inv1);
        Og[(g + 8) * 64 + p1] = f2tf(O[j][3] * inv1);
    }
}

// ---------------------------------------------------------------------------
extern "C" void kernel_launch(void* const* d_in, const int* in_sizes, int n_in,
                              void* d_out, int out_size) {
    (void)in_sizes; (void)n_in; (void)out_size;
    const float* query = (const float*)d_in[0];
    const float* key_ = (const float*)d_in[1];
    const float* value = (const float*)d_in[2];
    const float* Wq = (const float*)d_in[3];
    const float* bq = (const float*)d_in[4];
    const float* Wk = (const float*)d_in[5];
    const float* bk = (const float*)d_in[6];
    const float* Wv = (const float*)d_in[7];
    const float* bv = (const float*)d_in[8];
    const float* Wo = (const float*)d_in[9];
    const float* bo = (const float*)d_in[10];
    const float* bias_table = (const float*)d_in[11];
    const float* offset = (const float*)d_in[12];
    float* out = (float*)d_out;

    cudaFuncSetAttribute(gemm_tc<0, 1>,
                         cudaFuncAttributeMaxDynamicSharedMemorySize, SMEM_GEMM);
    cudaFuncSetAttribute(gemm_tc<1, 0>,
                         cudaFuncAttributeMaxDynamicSharedMemorySize, SMEM_GEMM);
    cudaFuncSetAttribute(attn_tc, cudaFuncAttributeMaxDynamicSharedMemorySize,
                         SMEM_ATTN);

    bias_kernel<<<32, 256>>>(bias_table, offset);
    conv_perm3<<<2048, 256>>>(query, key_, value);
    conv_perm4<<<1024, 256>>>(Wq, Wk, Wv, Wo);

    dim3 ggrid(Ec / 64, Mc / 128, 3);  // QKV fused: (16, 64, 3)
    gemm_tc<0, 1><<<ggrid, 256, SMEM_GEMM>>>(bq, bk, bv, nullptr);

    dim3 agrid(Tc / 128, Bc * Hc);  // (8, 128)
    attn_tc<<<agrid, 256, SMEM_ATTN>>>();

    dim3 ogrid(Ec / 64, Mc / 128, 1);
    gemm_tc<1, 0><<<ogrid, 256, SMEM_GEMM>>>(bo, nullptr, nullptr, out);
}